// round 9
// baseline (speedup 1.0000x reference)
#include <cuda_runtime.h>

#define BB   128
#define VV   256
#define FF   64
#define NS   4
#define NLR  64
#define NSLR 68
#define KNB  40
#define NOUT 128
#define KOUT 192

// ---------------- scratch ----------------------------------------------------
__device__ float g_mx  [BB * FF];
__device__ float g_s   [BB * VV * NS];
__device__ float g_lr  [BB * VV * NLR];
__device__ int   g_nidx[BB * VV * KNB];
__device__ float g_nw  [BB * VV * KNB];
__device__ float g_bb  [BB * NOUT];               // b_out + mx @ W_out[64:128]
__device__ float g_fpT [BB * KOUT * VV];          // transposed fp: [b][k][v]
__device__ float g_Wd  [KOUT * 2 * NOUT];         // W reordered + duplicated pairs

// ---------------- packed f32x2 helpers ---------------------------------------
typedef unsigned long long ull;
__device__ __forceinline__ ull pack2(float lo, float hi) {
    ull r; asm("mov.b64 %0, {%1, %2};" : "=l"(r) : "f"(lo), "f"(hi)); return r;
}
__device__ __forceinline__ void unpack2(ull v, float& lo, float& hi) {
    asm("mov.b64 {%0, %1}, %2;" : "=f"(lo), "=f"(hi) : "l"(v));
}
__device__ __forceinline__ void fma2(ull& d, ull a, ull b) {
    asm("fma.rn.f32x2 %0, %1, %2, %0;" : "+l"(d) : "l"(a), "l"(b));
}

// ============ K_WDUP: W reordered (skip mx rows) + duplicated =================
__global__ void k_wdup(const float* __restrict__ W) {
    int k = blockIdx.x;                 // 0..191 logical
    int c = threadIdx.x;                // 0..127
    int ksrc = (k < 64) ? k : (k + 64);
    float w = W[ksrc * NOUT + c];
    *(float2*)&g_Wd[k * 2 * NOUT + 2 * c] = make_float2(w, w);
}

// ============ K_FRONT: mean + slr GEMM + out-bias + x-transpose ==============
#define XSP 65
#define KF_SMEM ((VV * XSP + 128 * NSLR + 64 + 256 + NSLR) * 4)
__global__ void k_front(const float* __restrict__ x,
                        const float* __restrict__ W,
                        const float* __restrict__ bias,
                        const float* __restrict__ W_out,
                        const float* __restrict__ b_out) {
    extern __shared__ float sh[];
    float* xs   = sh;                       // [256][65]
    float* Wsh  = xs + VV * XSP;            // [128][68]
    float* mean = Wsh + 128 * NSLR;         // [64]
    float* red  = mean + 64;                // [256]
    float* cc   = red + 256;                // [68]
    int b = blockIdx.x;
    int t = threadIdx.x;

    const float* xb = x + (size_t)b * VV * FF;
    for (int e = t; e < VV * FF; e += 256) {
        int row = e >> 6, c = e & 63;
        xs[row * XSP + c] = xb[e];
    }
    for (int e = t; e < 128 * NSLR; e += 256) Wsh[e] = W[e];
    __syncthreads();

    // x-part of transposed fp: g_fpT[b][k][v] = x[b][v][k], k<64
    {
        float* dst = g_fpT + (size_t)b * KOUT * VV;
        for (int e = t; e < FF * VV; e += 256) {
            int k = e >> 8, v = e & 255;
            dst[e] = xs[v * XSP + k];
        }
    }

    {
        int f = t & 63, vg = t >> 6;
        float acc = 0.f;
        #pragma unroll 8
        for (int v = vg * 64; v < vg * 64 + 64; v++) acc += xs[v * XSP + f];
        red[vg * 64 + f] = acc;
    }
    __syncthreads();
    if (t < 64) {
        float m = (red[t] + red[64 + t] + red[128 + t] + red[192 + t]) * (1.0f / VV);
        mean[t] = m;
        g_mx[b * FF + t] = m;
    }
    __syncthreads();

    if (t < NSLR) {
        float acc = bias[t];
        #pragma unroll 8
        for (int k = 0; k < 64; k++) acc += mean[k] * Wsh[(64 + k) * NSLR + t];
        cc[t] = acc;
    }
    if (t < NOUT) {
        float acc = b_out[t];
        const float* wr = W_out + 64 * NOUT + t;
        #pragma unroll 16
        for (int k = 0; k < 64; k++) acc += mean[k] * wr[k * NOUT];
        g_bb[b * NOUT + t] = acc;
    }
    __syncthreads();

    int rg = t >> 2;
    int cg = t & 3;
    float acc[4][17];
    #pragma unroll
    for (int u = 0; u < 17; u++) {
        float c0 = cc[cg * 17 + u];
        #pragma unroll
        for (int q = 0; q < 4; q++) acc[q][u] = c0;
    }
    const float* xr = xs + (rg * 4) * XSP;
    #pragma unroll 2
    for (int k = 0; k < 64; k++) {
        float a0 = xr[k], a1 = xr[XSP + k], a2 = xr[2 * XSP + k], a3 = xr[3 * XSP + k];
        const float* wrow = Wsh + k * NSLR + cg * 17;
        #pragma unroll
        for (int u = 0; u < 17; u++) {
            float w = wrow[u];
            acc[0][u] += a0 * w; acc[1][u] += a1 * w;
            acc[2][u] += a2 * w; acc[3][u] += a3 * w;
        }
    }
    #pragma unroll
    for (int q = 0; q < 4; q++) {
        int bv = b * VV + rg * 4 + q;
        #pragma unroll
        for (int u = 0; u < 17; u++) {
            int col = cg * 17 + u;
            float v = fmaxf(acc[q][u], 0.f);
            if (col < NS) g_s [bv * NS  + col]       = v;
            else          g_lr[bv * NLR + col - NS]  = v;
        }
    }
}

// ============ K_SEL: warp-per-row top-40 by (d2, idx) ========================
__global__ void k_sel() {
    __shared__ float4 s_sh[VV];
    int b = blockIdx.x >> 5;
    int i = ((blockIdx.x & 31) << 3) + (threadIdx.x >> 5);
    int l = threadIdx.x & 31;
    if (threadIdx.x < VV)
        s_sh[threadIdx.x] = ((const float4*)g_s)[b * VV + threadIdx.x];
    __syncthreads();

    float4 sv = s_sh[i];
    float d2[8]; unsigned bits[8];
    #pragma unroll
    for (int q = 0; q < 8; q++) {
        float4 sj = s_sh[q * 32 + l];
        float dx = sv.x - sj.x, dy = sv.y - sj.y, dz = sv.z - sj.z, dw = sv.w - sj.w;
        d2[q] = dx * dx + dy * dy + dz * dz + dw * dw;
        bits[q] = __float_as_uint(d2[q]);
    }
    unsigned lo = 0u, hi = 0xFFFFFFFFu;
    #pragma unroll 1
    for (int it = 0; it < 32; it++) {
        unsigned mid = lo + ((hi - lo) >> 1);
        int c = 0;
        #pragma unroll
        for (int q = 0; q < 8; q++) c += (bits[q] <= mid);
        c = __reduce_add_sync(0xFFFFFFFFu, c);
        if (c >= KNB) hi = mid; else lo = mid + 1u;
    }
    unsigned thr = lo;
    int cl = 0;
    #pragma unroll
    for (int q = 0; q < 8; q++) cl += (bits[q] < thr);
    cl = __reduce_add_sync(0xFFFFFFFFu, cl);
    int need = KNB - cl;
    int jlo = 0, jhi = VV - 1;
    #pragma unroll 1
    for (int it = 0; it < 8; it++) {
        int jm = (jlo + jhi) >> 1;
        int c = 0;
        #pragma unroll
        for (int q = 0; q < 8; q++) c += (bits[q] == thr && (q * 32 + l) <= jm);
        c = __reduce_add_sync(0xFFFFFFFFu, c);
        if (c >= need) jhi = jm; else jlo = jm + 1;
    }
    int jthr = jlo;

    int row = b * VV + i;
    int base = 0;
    #pragma unroll
    for (int q = 0; q < 8; q++) {
        int j = q * 32 + l;
        bool sel = (bits[q] < thr) || (bits[q] == thr && j <= jthr);
        unsigned bal = __ballot_sync(0xFFFFFFFFu, sel);
        if (sel) {
            int pos = base + __popc(bal & ((1u << l) - 1u));
            g_nidx[row * KNB + pos] = j;
            g_nw  [row * KNB + pos] = __expf(-10.0f * d2[q]);
        }
        base += __popc(bal);
    }
}

// ============ K_AGG: thread-per-row weighted mean/max -> transposed fpT ======
#define LRP 68
#define SIP 257
#define KA_SMEM ((VV * LRP + 2 * KNB * SIP) * 4)
__global__ void k_agg() {
    extern __shared__ float sh[];
    float* lr_sh = sh;                       // [256][68]
    float* sw    = sh + VV * LRP;            // [40][257]
    int*   sidx  = (int*)(sw + KNB * SIP);   // [40][257]
    int b = blockIdx.x;
    int i = threadIdx.x;

    const float* lrg = g_lr + (size_t)b * VV * NLR;
    for (int e = i; e < VV * NLR; e += VV) {
        int r = e >> 6, c = e & 63;
        lr_sh[r * LRP + c] = lrg[e];
    }
    const int*   gi = g_nidx + (size_t)b * VV * KNB;
    const float* gw = g_nw   + (size_t)b * VV * KNB;
    for (int e = i; e < VV * KNB; e += VV) {
        int r = e / KNB, k = e - r * KNB;
        sidx[k * SIP + r] = gi[e];
        sw  [k * SIP + r] = gw[e];
    }
    __syncthreads();

    // dst[c*256 + i]: lanes i consecutive -> coalesced stores per feature c
    float* dm = g_fpT + (size_t)b * KOUT * VV + (size_t)64  * VV + i;
    float* dx = g_fpT + (size_t)b * KOUT * VV + (size_t)128 * VV + i;
    #pragma unroll
    for (int c0 = 0; c0 < NLR; c0 += 16) {
        float m[16], mx[16];
        #pragma unroll
        for (int f = 0; f < 16; f++) { m[f] = 0.f; mx[f] = 0.f; }
        for (int k = 0; k < KNB; k++) {
            int   j = sidx[k * SIP + i];
            float w = sw  [k * SIP + i];
            const float4* rowp = (const float4*)&lr_sh[j * LRP + c0];
            #pragma unroll
            for (int qq = 0; qq < 4; qq++) {
                float4 lv = rowp[qq];
                float v0 = lv.x * w, v1 = lv.y * w, v2 = lv.z * w, v3 = lv.w * w;
                m [qq*4+0] += v0; m [qq*4+1] += v1; m [qq*4+2] += v2; m [qq*4+3] += v3;
                mx[qq*4+0] = fmaxf(mx[qq*4+0], v0);
                mx[qq*4+1] = fmaxf(mx[qq*4+1], v1);
                mx[qq*4+2] = fmaxf(mx[qq*4+2], v2);
                mx[qq*4+3] = fmaxf(mx[qq*4+3], v3);
            }
        }
        #pragma unroll
        for (int f = 0; f < 16; f++) {
            dm[(c0 + f) * VV] = m[f] * (1.0f / KNB);
            dx[(c0 + f) * VV] = mx[f];
        }
    }
}

// ============ K_OUT: out = relu(fpT^T @ W + bb) ==============================
// 64 rows x 128 cols per block (grid 512), 128 threads, 4 blocks/SM.
// Thread tile: 8 rows (4 f32x2 row-pairs) x 8 cols.
// A row-pairs via direct LDS.64; W dup-pairs via direct LDG.128 on g_Wd.
// Zero pack-MOVs, zero index-select ALU in the loop.
#define ROWS_O 64
#define KO_SMEM ((KOUT * ROWS_O + NOUT) * 4)
__global__ void k_out(float* __restrict__ out) {
    extern __shared__ float sh[];
    float* fs  = sh;                     // [192][64]
    float* bbs = fs + KOUT * ROWS_O;     // [128]
    int t   = threadIdx.x;
    int bv0 = blockIdx.x * ROWS_O;
    int b   = bv0 >> 8;

    const float* src = g_fpT + (size_t)b * KOUT * VV + (bv0 & 255);
    #pragma unroll 12
    for (int e = t; e < KOUT * ROWS_O; e += 128) {
        int k = e >> 6, r = e & 63;
        fs[e] = src[k * VV + r];
    }
    bbs[t] = g_bb[b * NOUT + t];
    __syncthreads();

    int rg = t >> 4;     // 8 rowgroups x 8 rows
    int cg = t & 15;     // 16 colgroups x 8 cols

    ull acc[4][8];       // [rowpair][col]
    #pragma unroll
    for (int c = 0; c < 8; c++) {
        float bv = bbs[cg * 8 + c];
        ull bp = pack2(bv, bv);
        #pragma unroll
        for (int rp = 0; rp < 4; rp++) acc[rp][c] = bp;
    }

    const float* fb = fs + rg * 8;
    const ull*   wd = (const ull*)(g_Wd) + cg * 8;   // 8 dup-pairs per colgroup

    #pragma unroll 4
    for (int k = 0; k < KOUT; k++) {
        const float* ab = fb + k * ROWS_O;
        ull a0 = *(const ull*)(ab);
        ull a1 = *(const ull*)(ab + 2);
        ull a2 = *(const ull*)(ab + 4);
        ull a3 = *(const ull*)(ab + 6);
        const ull* wk = wd + (size_t)k * NOUT;       // 128 ull per k row
        #pragma unroll
        for (int c = 0; c < 8; c += 2) {
            ull w0, w1;
            asm("ld.global.nc.v2.u64 {%0, %1}, [%2];"
                : "=l"(w0), "=l"(w1) : "l"(wk + c));
            fma2(acc[0][c],   a0, w0); fma2(acc[1][c],   a1, w0);
            fma2(acc[2][c],   a2, w0); fma2(acc[3][c],   a3, w0);
            fma2(acc[0][c+1], a0, w1); fma2(acc[1][c+1], a1, w1);
            fma2(acc[2][c+1], a2, w1); fma2(acc[3][c+1], a3, w1);
        }
    }

    #pragma unroll
    for (int rp = 0; rp < 4; rp++) {
        float lo[8], hi[8];
        #pragma unroll
        for (int c = 0; c < 8; c++) unpack2(acc[rp][c], lo[c], hi[c]);
        float4 o0a, o0b, o1a, o1b;
        o0a.x = fmaxf(lo[0], 0.f); o0a.y = fmaxf(lo[1], 0.f);
        o0a.z = fmaxf(lo[2], 0.f); o0a.w = fmaxf(lo[3], 0.f);
        o0b.x = fmaxf(lo[4], 0.f); o0b.y = fmaxf(lo[5], 0.f);
        o0b.z = fmaxf(lo[6], 0.f); o0b.w = fmaxf(lo[7], 0.f);
        o1a.x = fmaxf(hi[0], 0.f); o1a.y = fmaxf(hi[1], 0.f);
        o1a.z = fmaxf(hi[2], 0.f); o1a.w = fmaxf(hi[3], 0.f);
        o1b.x = fmaxf(hi[4], 0.f); o1b.y = fmaxf(hi[5], 0.f);
        o1b.z = fmaxf(hi[6], 0.f); o1b.w = fmaxf(hi[7], 0.f);
        int r0 = bv0 + rg * 8 + rp * 2;
        float* op0 = out + (size_t)r0 * NOUT + cg * 8;
        float* op1 = op0 + NOUT;
        ((float4*)op0)[0] = o0a; ((float4*)op0)[1] = o0b;
        ((float4*)op1)[0] = o1a; ((float4*)op1)[1] = o1b;
    }
}

// ---------------- launch ------------------------------------------------------
extern "C" void kernel_launch(void* const* d_in, const int* in_sizes, int n_in,
                              void* d_out, int out_size) {
    const float* x     = (const float*)d_in[0];
    const float* W_slr = (const float*)d_in[1];
    const float* b_slr = (const float*)d_in[2];
    const float* W_out = (const float*)d_in[3];
    const float* b_out = (const float*)d_in[4];
    float* out = (float*)d_out;

    static bool attr_done = false;
    if (!attr_done) {
        cudaFuncSetAttribute(k_front, cudaFuncAttributeMaxDynamicSharedMemorySize, KF_SMEM);
        cudaFuncSetAttribute(k_agg,   cudaFuncAttributeMaxDynamicSharedMemorySize, KA_SMEM);
        cudaFuncSetAttribute(k_out,   cudaFuncAttributeMaxDynamicSharedMemorySize, KO_SMEM);
        attr_done = true;
    }

    k_wdup <<<KOUT, NOUT>>>(W_out);
    k_front<<<BB, 256, KF_SMEM>>>(x, W_slr, b_slr, W_out, b_out);
    k_sel  <<<BB * VV / 8, 256>>>();
    k_agg  <<<BB, VV, KA_SMEM>>>();
    k_out  <<<BB * VV / ROWS_O, 128, KO_SMEM>>>(out);
}

// round 10
// speedup vs baseline: 1.4188x; 1.4188x over previous
#include <cuda_runtime.h>

#define BB   128
#define VV   256
#define FF   64
#define NS   4
#define NLR  64
#define NSLR 68
#define KNB  40
#define NOUT 128
#define KOUT 192

// ---------------- scratch ----------------------------------------------------
__device__ float g_mx  [BB * FF];
__device__ float g_s   [BB * VV * NS];
__device__ float g_lr  [BB * VV * NLR];
__device__ int   g_nidx[BB * VV * KNB];
__device__ float g_nw  [BB * VV * KNB];
__device__ float g_bb  [BB * NOUT];               // b_out + mx @ W_out[64:128]
__device__ float g_fpT [BB * KOUT * VV];          // transposed fp: [b][k][v]

// ---------------- packed f32x2 helpers ---------------------------------------
typedef unsigned long long ull;
__device__ __forceinline__ ull pack2(float lo, float hi) {
    ull r; asm("mov.b64 %0, {%1, %2};" : "=l"(r) : "f"(lo), "f"(hi)); return r;
}
__device__ __forceinline__ void unpack2(ull v, float& lo, float& hi) {
    asm("mov.b64 {%0, %1}, %2;" : "=f"(lo), "=f"(hi) : "l"(v));
}
__device__ __forceinline__ void fma2(ull& d, ull a, ull b) {
    asm("fma.rn.f32x2 %0, %1, %2, %0;" : "+l"(d) : "l"(a), "l"(b));
}

// ============ K_FRONT: mean + slr GEMM + out-bias + x-transpose ==============
#define XSP 65
#define KF_SMEM ((VV * XSP + 128 * NSLR + 64 + 256 + NSLR) * 4)
__global__ void k_front(const float* __restrict__ x,
                        const float* __restrict__ W,
                        const float* __restrict__ bias,
                        const float* __restrict__ W_out,
                        const float* __restrict__ b_out) {
    extern __shared__ float sh[];
    float* xs   = sh;                       // [256][65]
    float* Wsh  = xs + VV * XSP;            // [128][68]
    float* mean = Wsh + 128 * NSLR;         // [64]
    float* red  = mean + 64;                // [256]
    float* cc   = red + 256;                // [68]
    int b = blockIdx.x;
    int t = threadIdx.x;

    const float* xb = x + (size_t)b * VV * FF;
    for (int e = t; e < VV * FF; e += 256) {
        int row = e >> 6, c = e & 63;
        xs[row * XSP + c] = xb[e];
    }
    for (int e = t; e < 128 * NSLR; e += 256) Wsh[e] = W[e];
    __syncthreads();

    // x-part of transposed fp: g_fpT[b][k][v] = x[b][v][k], k<64
    {
        float* dst = g_fpT + (size_t)b * KOUT * VV;
        for (int e = t; e < FF * VV; e += 256) {
            int k = e >> 8, v = e & 255;
            dst[e] = xs[v * XSP + k];
        }
    }

    {
        int f = t & 63, vg = t >> 6;
        float acc = 0.f;
        #pragma unroll 8
        for (int v = vg * 64; v < vg * 64 + 64; v++) acc += xs[v * XSP + f];
        red[vg * 64 + f] = acc;
    }
    __syncthreads();
    if (t < 64) {
        float m = (red[t] + red[64 + t] + red[128 + t] + red[192 + t]) * (1.0f / VV);
        mean[t] = m;
        g_mx[b * FF + t] = m;
    }
    __syncthreads();

    if (t < NSLR) {
        float acc = bias[t];
        #pragma unroll 8
        for (int k = 0; k < 64; k++) acc += mean[k] * Wsh[(64 + k) * NSLR + t];
        cc[t] = acc;
    }
    if (t < NOUT) {
        float acc = b_out[t];
        const float* wr = W_out + 64 * NOUT + t;
        #pragma unroll 16
        for (int k = 0; k < 64; k++) acc += mean[k] * wr[k * NOUT];
        g_bb[b * NOUT + t] = acc;
    }
    __syncthreads();

    int rg = t >> 2;
    int cg = t & 3;
    float acc[4][17];
    #pragma unroll
    for (int u = 0; u < 17; u++) {
        float c0 = cc[cg * 17 + u];
        #pragma unroll
        for (int q = 0; q < 4; q++) acc[q][u] = c0;
    }
    const float* xr = xs + (rg * 4) * XSP;
    #pragma unroll 2
    for (int k = 0; k < 64; k++) {
        float a0 = xr[k], a1 = xr[XSP + k], a2 = xr[2 * XSP + k], a3 = xr[3 * XSP + k];
        const float* wrow = Wsh + k * NSLR + cg * 17;
        #pragma unroll
        for (int u = 0; u < 17; u++) {
            float w = wrow[u];
            acc[0][u] += a0 * w; acc[1][u] += a1 * w;
            acc[2][u] += a2 * w; acc[3][u] += a3 * w;
        }
    }
    #pragma unroll
    for (int q = 0; q < 4; q++) {
        int bv = b * VV + rg * 4 + q;
        #pragma unroll
        for (int u = 0; u < 17; u++) {
            int col = cg * 17 + u;
            float v = fmaxf(acc[q][u], 0.f);
            if (col < NS) g_s [bv * NS  + col]       = v;
            else          g_lr[bv * NLR + col - NS]  = v;
        }
    }
}

// ============ K_SEL: warp-per-row top-40 by (d2, idx) ========================
__global__ void k_sel() {
    __shared__ float4 s_sh[VV];
    int b = blockIdx.x >> 5;
    int i = ((blockIdx.x & 31) << 3) + (threadIdx.x >> 5);
    int l = threadIdx.x & 31;
    if (threadIdx.x < VV)
        s_sh[threadIdx.x] = ((const float4*)g_s)[b * VV + threadIdx.x];
    __syncthreads();

    float4 sv = s_sh[i];
    float d2[8]; unsigned bits[8];
    #pragma unroll
    for (int q = 0; q < 8; q++) {
        float4 sj = s_sh[q * 32 + l];
        float dx = sv.x - sj.x, dy = sv.y - sj.y, dz = sv.z - sj.z, dw = sv.w - sj.w;
        d2[q] = dx * dx + dy * dy + dz * dz + dw * dw;
        bits[q] = __float_as_uint(d2[q]);
    }
    unsigned lo = 0u, hi = 0xFFFFFFFFu;
    #pragma unroll 1
    for (int it = 0; it < 32; it++) {
        unsigned mid = lo + ((hi - lo) >> 1);
        int c = 0;
        #pragma unroll
        for (int q = 0; q < 8; q++) c += (bits[q] <= mid);
        c = __reduce_add_sync(0xFFFFFFFFu, c);
        if (c >= KNB) hi = mid; else lo = mid + 1u;
    }
    unsigned thr = lo;
    int cl = 0;
    #pragma unroll
    for (int q = 0; q < 8; q++) cl += (bits[q] < thr);
    cl = __reduce_add_sync(0xFFFFFFFFu, cl);
    int need = KNB - cl;
    int jlo = 0, jhi = VV - 1;
    #pragma unroll 1
    for (int it = 0; it < 8; it++) {
        int jm = (jlo + jhi) >> 1;
        int c = 0;
        #pragma unroll
        for (int q = 0; q < 8; q++) c += (bits[q] == thr && (q * 32 + l) <= jm);
        c = __reduce_add_sync(0xFFFFFFFFu, c);
        if (c >= need) jhi = jm; else jlo = jm + 1;
    }
    int jthr = jlo;

    int row = b * VV + i;
    int base = 0;
    #pragma unroll
    for (int q = 0; q < 8; q++) {
        int j = q * 32 + l;
        bool sel = (bits[q] < thr) || (bits[q] == thr && j <= jthr);
        unsigned bal = __ballot_sync(0xFFFFFFFFu, sel);
        if (sel) {
            int pos = base + __popc(bal & ((1u << l) - 1u));
            g_nidx[row * KNB + pos] = j;
            g_nw  [row * KNB + pos] = __expf(-10.0f * d2[q]);
        }
        base += __popc(bal);
    }
}

// ============ K_AGG: thread-per-row weighted mean/max, 2 blocks/batch ========
// Block handles 128 rows; 256 threads: thread = (row = t&127, half = t>>7),
// each thread does 2 chunks of 16 features. smem 111KB -> 2 blocks/SM.
#define LRP 68
#define SIP 129
#define HR  128
#define KA_SMEM ((VV * LRP + 2 * KNB * SIP) * 4)
__global__ void k_agg() {
    extern __shared__ float sh[];
    float* lr_sh = sh;                       // [256][68]
    float* sw    = sh + VV * LRP;            // [40][129]
    int*   sidx  = (int*)(sw + KNB * SIP);   // [40][129]
    int b = blockIdx.x >> 1;
    int q = blockIdx.x & 1;
    int t = threadIdx.x;

    const float* lrg = g_lr + (size_t)b * VV * NLR;
    for (int e = t; e < VV * NLR; e += 256) {
        int r = e >> 6, c = e & 63;
        lr_sh[r * LRP + c] = lrg[e];
    }
    const int*   gi = g_nidx + ((size_t)b * VV + q * HR) * KNB;
    const float* gw = g_nw   + ((size_t)b * VV + q * HR) * KNB;
    for (int e = t; e < HR * KNB; e += 256) {
        int r = e / KNB, k = e - r * KNB;
        sidx[k * SIP + r] = gi[e];
        sw  [k * SIP + r] = gw[e];
    }
    __syncthreads();

    int il = t & 127;                        // local row
    int i  = q * HR + il;                    // global row in batch
    int ch = (t >> 7) * 32;                  // feature chunk base (0 or 32)

    float* dm = g_fpT + (size_t)b * KOUT * VV + (size_t)64  * VV + i;
    float* dx = g_fpT + (size_t)b * KOUT * VV + (size_t)128 * VV + i;
    #pragma unroll
    for (int cc = 0; cc < 32; cc += 16) {
        int c0 = ch + cc;
        float m[16], mx[16];
        #pragma unroll
        for (int f = 0; f < 16; f++) { m[f] = 0.f; mx[f] = 0.f; }
        for (int k = 0; k < KNB; k++) {
            int   j = sidx[k * SIP + il];
            float w = sw  [k * SIP + il];
            const float4* rowp = (const float4*)&lr_sh[j * LRP + c0];
            #pragma unroll
            for (int qq = 0; qq < 4; qq++) {
                float4 lv = rowp[qq];
                float v0 = lv.x * w, v1 = lv.y * w, v2 = lv.z * w, v3 = lv.w * w;
                m [qq*4+0] += v0; m [qq*4+1] += v1; m [qq*4+2] += v2; m [qq*4+3] += v3;
                mx[qq*4+0] = fmaxf(mx[qq*4+0], v0);
                mx[qq*4+1] = fmaxf(mx[qq*4+1], v1);
                mx[qq*4+2] = fmaxf(mx[qq*4+2], v2);
                mx[qq*4+3] = fmaxf(mx[qq*4+3], v3);
            }
        }
        #pragma unroll
        for (int f = 0; f < 16; f++) {
            dm[(c0 + f) * VV] = m[f] * (1.0f / KNB);
            dx[(c0 + f) * VV] = mx[f];
        }
    }
}

// ============ K_OUT: out = relu(fpT^T @ W + bb)  (R8 proven version) =========
// 32 rows x 128 cols per block, 1024 blocks, 128 threads.
// Thread tile: 8 rows (4 f32x2 pairs) x 4 cols = 16 fma2 per k.
#define ROWS_O 32
#define KO_SMEM ((KOUT * ROWS_O + NOUT) * 4)
__global__ void k_out(const float* __restrict__ W,
                      float* __restrict__ out) {
    extern __shared__ float sh[];
    float* fs  = sh;                     // [192][32]
    float* bbs = fs + KOUT * ROWS_O;     // [128]
    int t   = threadIdx.x;
    int bv0 = blockIdx.x * ROWS_O;
    int b   = bv0 >> 8;

    const float* src = g_fpT + (size_t)b * KOUT * VV + (bv0 & 255);
    #pragma unroll 12
    for (int e = t; e < KOUT * ROWS_O; e += 128) {
        int k = e >> 5, r = e & 31;
        fs[e] = src[k * VV + r];
    }
    bbs[t] = g_bb[b * NOUT + t];
    __syncthreads();

    int rg = t >> 5;     // 4 rowgroups x 8 rows
    int cg = t & 31;     // 32 colgroups x 4 cols

    ull acc[4][4];       // [rowpair][col]
    #pragma unroll
    for (int c = 0; c < 4; c++) {
        float bv = bbs[cg * 4 + c];
        ull bp = pack2(bv, bv);
        #pragma unroll
        for (int rp = 0; rp < 4; rp++) acc[rp][c] = bp;
    }

    const float*  fb = fs + rg * 8;
    const float4* wp = (const float4*)(W) + cg;

    #pragma unroll 4
    for (int k = 0; k < KOUT; k++) {
        int ksrc = (k < 64) ? k : (k + 64);       // skip mx block (folded in bb)
        const float* base = fb + k * ROWS_O;
        ull a0 = *(const ull*)(base);
        ull a1 = *(const ull*)(base + 2);
        ull a2 = *(const ull*)(base + 4);
        ull a3 = *(const ull*)(base + 6);
        float4 w4 = __ldg(wp + (size_t)ksrc * 32);
        ull w0 = pack2(w4.x, w4.x), w1 = pack2(w4.y, w4.y);
        ull w2 = pack2(w4.z, w4.z), w3 = pack2(w4.w, w4.w);
        fma2(acc[0][0], a0, w0); fma2(acc[1][0], a1, w0); fma2(acc[2][0], a2, w0); fma2(acc[3][0], a3, w0);
        fma2(acc[0][1], a0, w1); fma2(acc[1][1], a1, w1); fma2(acc[2][1], a2, w1); fma2(acc[3][1], a3, w1);
        fma2(acc[0][2], a0, w2); fma2(acc[1][2], a1, w2); fma2(acc[2][2], a2, w2); fma2(acc[3][2], a3, w2);
        fma2(acc[0][3], a0, w3); fma2(acc[1][3], a1, w3); fma2(acc[2][3], a2, w3); fma2(acc[3][3], a3, w3);
    }

    #pragma unroll
    for (int rp = 0; rp < 4; rp++) {
        float lo0, hi0, lo1, hi1, lo2, hi2, lo3, hi3;
        unpack2(acc[rp][0], lo0, hi0);
        unpack2(acc[rp][1], lo1, hi1);
        unpack2(acc[rp][2], lo2, hi2);
        unpack2(acc[rp][3], lo3, hi3);
        float4 o0, o1;
        o0.x = fmaxf(lo0, 0.f); o0.y = fmaxf(lo1, 0.f);
        o0.z = fmaxf(lo2, 0.f); o0.w = fmaxf(lo3, 0.f);
        o1.x = fmaxf(hi0, 0.f); o1.y = fmaxf(hi1, 0.f);
        o1.z = fmaxf(hi2, 0.f); o1.w = fmaxf(hi3, 0.f);
        int r0 = bv0 + rg * 8 + rp * 2;
        *(float4*)(out + (size_t)r0 * NOUT + cg * 4)       = o0;
        *(float4*)(out + (size_t)(r0 + 1) * NOUT + cg * 4) = o1;
    }
}

// ---------------- launch ------------------------------------------------------
extern "C" void kernel_launch(void* const* d_in, const int* in_sizes, int n_in,
                              void* d_out, int out_size) {
    const float* x     = (const float*)d_in[0];
    const float* W_slr = (const float*)d_in[1];
    const float* b_slr = (const float*)d_in[2];
    const float* W_out = (const float*)d_in[3];
    const float* b_out = (const float*)d_in[4];
    float* out = (float*)d_out;

    static bool attr_done = false;
    if (!attr_done) {
        cudaFuncSetAttribute(k_front, cudaFuncAttributeMaxDynamicSharedMemorySize, KF_SMEM);
        cudaFuncSetAttribute(k_agg,   cudaFuncAttributeMaxDynamicSharedMemorySize, KA_SMEM);
        cudaFuncSetAttribute(k_out,   cudaFuncAttributeMaxDynamicSharedMemorySize, KO_SMEM);
        attr_done = true;
    }

    k_front<<<BB, 256, KF_SMEM>>>(x, W_slr, b_slr, W_out, b_out);
    k_sel  <<<BB * VV / 8, 256>>>();
    k_agg  <<<BB * 2, 256, KA_SMEM>>>();
    k_out  <<<BB * VV / ROWS_O, 128, KO_SMEM>>>(W_out, out);
}

// round 11
// speedup vs baseline: 1.4881x; 1.0488x over previous
#include <cuda_runtime.h>

#define BB   128
#define VV   256
#define FF   64
#define NS   4
#define NLR  64
#define NSLR 68
#define KNB  40
#define NOUT 128
#define KOUT 192

// ---------------- scratch ----------------------------------------------------
__device__ float g_mx  [BB * FF];
__device__ float g_s   [BB * VV * NS];
__device__ float g_lr  [BB * VV * NLR];
__device__ int   g_nidx[BB * VV * KNB];
__device__ float g_nw  [BB * VV * KNB];
__device__ float g_bb  [BB * NOUT];               // b_out + mx @ W_out[64:128]
__device__ float g_fpT [BB * KOUT * VV];          // transposed fp: [b][k][v]

// ---------------- packed f32x2 helpers ---------------------------------------
typedef unsigned long long ull;
__device__ __forceinline__ ull pack2(float lo, float hi) {
    ull r; asm("mov.b64 %0, {%1, %2};" : "=l"(r) : "f"(lo), "f"(hi)); return r;
}
__device__ __forceinline__ void unpack2(ull v, float& lo, float& hi) {
    asm("mov.b64 {%0, %1}, %2;" : "=f"(lo), "=f"(hi) : "l"(v));
}
__device__ __forceinline__ void fma2(ull& d, ull a, ull b) {
    asm("fma.rn.f32x2 %0, %1, %2, %0;" : "+l"(d) : "l"(a), "l"(b));
}

// ============ K_FRONT: mean + slr GEMM + out-bias + x-transpose ==============
#define XSP 65
#define KF_SMEM ((VV * XSP + 128 * NSLR + 64 + 256 + NSLR) * 4)
__global__ void k_front(const float* __restrict__ x,
                        const float* __restrict__ W,
                        const float* __restrict__ bias,
                        const float* __restrict__ W_out,
                        const float* __restrict__ b_out) {
    extern __shared__ float sh[];
    float* xs   = sh;                       // [256][65]
    float* Wsh  = xs + VV * XSP;            // [128][68]
    float* mean = Wsh + 128 * NSLR;         // [64]
    float* red  = mean + 64;                // [256]
    float* cc   = red + 256;                // [68]
    int b = blockIdx.x;
    int t = threadIdx.x;

    const float* xb = x + (size_t)b * VV * FF;
    for (int e = t; e < VV * FF; e += 256) {
        int row = e >> 6, c = e & 63;
        xs[row * XSP + c] = xb[e];
    }
    for (int e = t; e < 128 * NSLR; e += 256) Wsh[e] = W[e];
    __syncthreads();

    // x-part of transposed fp: g_fpT[b][k][v] = x[b][v][k], k<64
    {
        float* dst = g_fpT + (size_t)b * KOUT * VV;
        for (int e = t; e < FF * VV; e += 256) {
            int k = e >> 8, v = e & 255;
            dst[e] = xs[v * XSP + k];
        }
    }

    {
        int f = t & 63, vg = t >> 6;
        float acc = 0.f;
        #pragma unroll 8
        for (int v = vg * 64; v < vg * 64 + 64; v++) acc += xs[v * XSP + f];
        red[vg * 64 + f] = acc;
    }
    __syncthreads();
    if (t < 64) {
        float m = (red[t] + red[64 + t] + red[128 + t] + red[192 + t]) * (1.0f / VV);
        mean[t] = m;
        g_mx[b * FF + t] = m;
    }
    __syncthreads();

    if (t < NSLR) {
        float acc = bias[t];
        #pragma unroll 8
        for (int k = 0; k < 64; k++) acc += mean[k] * Wsh[(64 + k) * NSLR + t];
        cc[t] = acc;
    }
    if (t < NOUT) {
        float acc = b_out[t];
        const float* wr = W_out + 64 * NOUT + t;
        #pragma unroll 16
        for (int k = 0; k < 64; k++) acc += mean[k] * wr[k * NOUT];
        g_bb[b * NOUT + t] = acc;
    }
    __syncthreads();

    int rg = t >> 2;
    int cg = t & 3;
    float acc[4][17];
    #pragma unroll
    for (int u = 0; u < 17; u++) {
        float c0 = cc[cg * 17 + u];
        #pragma unroll
        for (int q = 0; q < 4; q++) acc[q][u] = c0;
    }
    const float* xr = xs + (rg * 4) * XSP;
    #pragma unroll 2
    for (int k = 0; k < 64; k++) {
        float a0 = xr[k], a1 = xr[XSP + k], a2 = xr[2 * XSP + k], a3 = xr[3 * XSP + k];
        const float* wrow = Wsh + k * NSLR + cg * 17;
        #pragma unroll
        for (int u = 0; u < 17; u++) {
            float w = wrow[u];
            acc[0][u] += a0 * w; acc[1][u] += a1 * w;
            acc[2][u] += a2 * w; acc[3][u] += a3 * w;
        }
    }
    #pragma unroll
    for (int q = 0; q < 4; q++) {
        int bv = b * VV + rg * 4 + q;
        #pragma unroll
        for (int u = 0; u < 17; u++) {
            int col = cg * 17 + u;
            float v = fmaxf(acc[q][u], 0.f);
            if (col < NS) g_s [bv * NS  + col]       = v;
            else          g_lr[bv * NLR + col - NS]  = v;
        }
    }
}

// ============ K_SEL: warp-per-row top-40 by (d2, idx) ========================
__global__ void k_sel() {
    __shared__ float4 s_sh[VV];
    int b = blockIdx.x >> 5;
    int i = ((blockIdx.x & 31) << 3) + (threadIdx.x >> 5);
    int l = threadIdx.x & 31;
    if (threadIdx.x < VV)
        s_sh[threadIdx.x] = ((const float4*)g_s)[b * VV + threadIdx.x];
    __syncthreads();

    float4 sv = s_sh[i];
    float d2[8]; unsigned bits[8];
    #pragma unroll
    for (int q = 0; q < 8; q++) {
        float4 sj = s_sh[q * 32 + l];
        float dx = sv.x - sj.x, dy = sv.y - sj.y, dz = sv.z - sj.z, dw = sv.w - sj.w;
        d2[q] = dx * dx + dy * dy + dz * dz + dw * dw;
        bits[q] = __float_as_uint(d2[q]);
    }
    unsigned lo = 0u, hi = 0xFFFFFFFFu;
    #pragma unroll 1
    for (int it = 0; it < 32; it++) {
        unsigned mid = lo + ((hi - lo) >> 1);
        int c = 0;
        #pragma unroll
        for (int q = 0; q < 8; q++) c += (bits[q] <= mid);
        c = __reduce_add_sync(0xFFFFFFFFu, c);
        if (c >= KNB) hi = mid; else lo = mid + 1u;
    }
    unsigned thr = lo;
    int cl = 0;
    #pragma unroll
    for (int q = 0; q < 8; q++) cl += (bits[q] < thr);
    cl = __reduce_add_sync(0xFFFFFFFFu, cl);
    int need = KNB - cl;
    int jlo = 0, jhi = VV - 1;
    #pragma unroll 1
    for (int it = 0; it < 8; it++) {
        int jm = (jlo + jhi) >> 1;
        int c = 0;
        #pragma unroll
        for (int q = 0; q < 8; q++) c += (bits[q] == thr && (q * 32 + l) <= jm);
        c = __reduce_add_sync(0xFFFFFFFFu, c);
        if (c >= need) jhi = jm; else jlo = jm + 1;
    }
    int jthr = jlo;

    int row = b * VV + i;
    int base = 0;
    #pragma unroll
    for (int q = 0; q < 8; q++) {
        int j = q * 32 + l;
        bool sel = (bits[q] < thr) || (bits[q] == thr && j <= jthr);
        unsigned bal = __ballot_sync(0xFFFFFFFFu, sel);
        if (sel) {
            int pos = base + __popc(bal & ((1u << l) - 1u));
            g_nidx[row * KNB + pos] = j;
            g_nw  [row * KNB + pos] = __expf(-10.0f * d2[q]);
        }
        base += __popc(bal);
    }
}

// ============ K_AGG: thread-per-row weighted mean/max, 2 blocks/batch ========
#define LRP 68
#define SIP 129
#define HR  128
#define KA_SMEM ((VV * LRP + 2 * KNB * SIP) * 4)
__global__ void k_agg() {
    extern __shared__ float sh[];
    float* lr_sh = sh;                       // [256][68]
    float* sw    = sh + VV * LRP;            // [40][129]
    int*   sidx  = (int*)(sw + KNB * SIP);   // [40][129]
    int b = blockIdx.x >> 1;
    int q = blockIdx.x & 1;
    int t = threadIdx.x;

    const float* lrg = g_lr + (size_t)b * VV * NLR;
    for (int e = t; e < VV * NLR; e += 256) {
        int r = e >> 6, c = e & 63;
        lr_sh[r * LRP + c] = lrg[e];
    }
    const int*   gi = g_nidx + ((size_t)b * VV + q * HR) * KNB;
    const float* gw = g_nw   + ((size_t)b * VV + q * HR) * KNB;
    for (int e = t; e < HR * KNB; e += 256) {
        int r = e / KNB, k = e - r * KNB;
        sidx[k * SIP + r] = gi[e];
        sw  [k * SIP + r] = gw[e];
    }
    __syncthreads();

    int il = t & 127;                        // local row
    int i  = q * HR + il;                    // global row in batch
    int ch = (t >> 7) * 32;                  // feature chunk base (0 or 32)

    float* dm = g_fpT + (size_t)b * KOUT * VV + (size_t)64  * VV + i;
    float* dx = g_fpT + (size_t)b * KOUT * VV + (size_t)128 * VV + i;
    #pragma unroll
    for (int cc = 0; cc < 32; cc += 16) {
        int c0 = ch + cc;
        float m[16], mx[16];
        #pragma unroll
        for (int f = 0; f < 16; f++) { m[f] = 0.f; mx[f] = 0.f; }
        for (int k = 0; k < KNB; k++) {
            int   j = sidx[k * SIP + il];
            float w = sw  [k * SIP + il];
            const float4* rowp = (const float4*)&lr_sh[j * LRP + c0];
            #pragma unroll
            for (int qq = 0; qq < 4; qq++) {
                float4 lv = rowp[qq];
                float v0 = lv.x * w, v1 = lv.y * w, v2 = lv.z * w, v3 = lv.w * w;
                m [qq*4+0] += v0; m [qq*4+1] += v1; m [qq*4+2] += v2; m [qq*4+3] += v3;
                mx[qq*4+0] = fmaxf(mx[qq*4+0], v0);
                mx[qq*4+1] = fmaxf(mx[qq*4+1], v1);
                mx[qq*4+2] = fmaxf(mx[qq*4+2], v2);
                mx[qq*4+3] = fmaxf(mx[qq*4+3], v3);
            }
        }
        #pragma unroll
        for (int f = 0; f < 16; f++) {
            dm[(c0 + f) * VV] = m[f] * (1.0f / KNB);
            dx[(c0 + f) * VV] = mx[f];
        }
    }
}

// ============ K_OUT: out = relu(fpT^T @ W + bb), prefetched W ================
// 32 rows x 128 cols per block, 1024 blocks (single wave @7/SM), 128 threads.
// Thread tile: 8 rows (4 f32x2 pairs) x 4 cols; W load software-pipelined.
#define ROWS_O 32
#define KO_SMEM ((KOUT * ROWS_O + NOUT) * 4)

#define KOUT_BODY(KIDX, W4)                                                     \
    {                                                                           \
        const float* base_ = fb + (KIDX) * ROWS_O;                              \
        ull a0 = *(const ull*)(base_);                                          \
        ull a1 = *(const ull*)(base_ + 2);                                      \
        ull a2 = *(const ull*)(base_ + 4);                                      \
        ull a3 = *(const ull*)(base_ + 6);                                      \
        ull w0 = pack2((W4).x, (W4).x), w1 = pack2((W4).y, (W4).y);             \
        ull w2 = pack2((W4).z, (W4).z), w3 = pack2((W4).w, (W4).w);             \
        fma2(acc[0][0], a0, w0); fma2(acc[1][0], a1, w0);                       \
        fma2(acc[2][0], a2, w0); fma2(acc[3][0], a3, w0);                       \
        fma2(acc[0][1], a0, w1); fma2(acc[1][1], a1, w1);                       \
        fma2(acc[2][1], a2, w1); fma2(acc[3][1], a3, w1);                       \
        fma2(acc[0][2], a0, w2); fma2(acc[1][2], a1, w2);                       \
        fma2(acc[2][2], a2, w2); fma2(acc[3][2], a3, w2);                       \
        fma2(acc[0][3], a0, w3); fma2(acc[1][3], a1, w3);                       \
        fma2(acc[2][3], a2, w3); fma2(acc[3][3], a3, w3);                       \
    }

__global__ __launch_bounds__(128, 7)
void k_out(const float* __restrict__ W,
           float* __restrict__ out) {
    extern __shared__ float sh[];
    float* fs  = sh;                     // [192][32]
    float* bbs = fs + KOUT * ROWS_O;     // [128]
    int t   = threadIdx.x;
    int bv0 = blockIdx.x * ROWS_O;
    int b   = bv0 >> 8;

    const float* src = g_fpT + (size_t)b * KOUT * VV + (bv0 & 255);
    #pragma unroll 12
    for (int e = t; e < KOUT * ROWS_O; e += 128) {
        int k = e >> 5, r = e & 31;
        fs[e] = src[k * VV + r];
    }
    bbs[t] = g_bb[b * NOUT + t];
    __syncthreads();

    int rg = t >> 5;     // 4 rowgroups x 8 rows
    int cg = t & 31;     // 32 colgroups x 4 cols

    ull acc[4][4];       // [rowpair][col]
    #pragma unroll
    for (int c = 0; c < 4; c++) {
        float bv = bbs[cg * 4 + c];
        ull bp = pack2(bv, bv);
        #pragma unroll
        for (int rp = 0; rp < 4; rp++) acc[rp][c] = bp;
    }

    const float*  fb = fs + rg * 8;
    const float4* wp = (const float4*)(W) + cg;

    // W rows: k<64 -> row k; k>=64 -> row k+64 (mx block folded into bb).
    float4 w4 = __ldg(wp);                            // row 0
    #pragma unroll 8
    for (int k = 0; k < 63; k++) {
        float4 wn = __ldg(wp + (size_t)(k + 1) * 32); // prefetch next row
        KOUT_BODY(k, w4);
        w4 = wn;
    }
    {
        float4 wn = __ldg(wp + (size_t)128 * 32);     // first row of 2nd region
        KOUT_BODY(63, w4);
        w4 = wn;
    }
    #pragma unroll 8
    for (int k = 64; k < 191; k++) {
        float4 wn = __ldg(wp + (size_t)(k + 65) * 32); // ksrc(k+1) = k+65
        KOUT_BODY(k, w4);
        w4 = wn;
    }
    KOUT_BODY(191, w4);

    #pragma unroll
    for (int rp = 0; rp < 4; rp++) {
        float lo0, hi0, lo1, hi1, lo2, hi2, lo3, hi3;
        unpack2(acc[rp][0], lo0, hi0);
        unpack2(acc[rp][1], lo1, hi1);
        unpack2(acc[rp][2], lo2, hi2);
        unpack2(acc[rp][3], lo3, hi3);
        float4 o0, o1;
        o0.x = fmaxf(lo0, 0.f); o0.y = fmaxf(lo1, 0.f);
        o0.z = fmaxf(lo2, 0.f); o0.w = fmaxf(lo3, 0.f);
        o1.x = fmaxf(hi0, 0.f); o1.y = fmaxf(hi1, 0.f);
        o1.z = fmaxf(hi2, 0.f); o1.w = fmaxf(hi3, 0.f);
        int r0 = bv0 + rg * 8 + rp * 2;
        *(float4*)(out + (size_t)r0 * NOUT + cg * 4)       = o0;
        *(float4*)(out + (size_t)(r0 + 1) * NOUT + cg * 4) = o1;
    }
}

// ---------------- launch ------------------------------------------------------
extern "C" void kernel_launch(void* const* d_in, const int* in_sizes, int n_in,
                              void* d_out, int out_size) {
    const float* x     = (const float*)d_in[0];
    const float* W_slr = (const float*)d_in[1];
    const float* b_slr = (const float*)d_in[2];
    const float* W_out = (const float*)d_in[3];
    const float* b_out = (const float*)d_in[4];
    float* out = (float*)d_out;

    static bool attr_done = false;
    if (!attr_done) {
        cudaFuncSetAttribute(k_front, cudaFuncAttributeMaxDynamicSharedMemorySize, KF_SMEM);
        cudaFuncSetAttribute(k_agg,   cudaFuncAttributeMaxDynamicSharedMemorySize, KA_SMEM);
        cudaFuncSetAttribute(k_out,   cudaFuncAttributeMaxDynamicSharedMemorySize, KO_SMEM);
        attr_done = true;
    }

    k_front<<<BB, 256, KF_SMEM>>>(x, W_slr, b_slr, W_out, b_out);
    k_sel  <<<BB * VV / 8, 256>>>();
    k_agg  <<<BB * 2, 256, KA_SMEM>>>();
    k_out  <<<BB * VV / ROWS_O, 128, KO_SMEM>>>(W_out, out);
}

// round 12
// speedup vs baseline: 1.6481x; 1.1075x over previous
#include <cuda_runtime.h>

#define BB   128
#define VV   256
#define FF   64
#define NS   4
#define NLR  64
#define NSLR 68
#define KNB  40
#define NOUT 128
#define KOUT 192

// ---------------- scratch ----------------------------------------------------
__device__ float g_mx  [BB * FF];
__device__ float g_s   [BB * VV * NS];
__device__ float g_lr  [BB * VV * NLR];
__device__ int   g_nidx[BB * VV * KNB];
__device__ float g_nw  [BB * VV * KNB];
__device__ float g_bb  [BB * NOUT];               // b_out + mx @ W_out[64:128]
__device__ float g_fpT [BB * KOUT * VV];          // transposed fp: [b][k][v]

// ---------------- packed f32x2 helpers ---------------------------------------
typedef unsigned long long ull;
__device__ __forceinline__ ull pack2(float lo, float hi) {
    ull r; asm("mov.b64 %0, {%1, %2};" : "=l"(r) : "f"(lo), "f"(hi)); return r;
}
__device__ __forceinline__ void unpack2(ull v, float& lo, float& hi) {
    asm("mov.b64 {%0, %1}, %2;" : "=f"(lo), "=f"(hi) : "l"(v));
}
__device__ __forceinline__ void fma2(ull& d, ull a, ull b) {
    asm("fma.rn.f32x2 %0, %1, %2, %0;" : "+l"(d) : "l"(a), "l"(b));
}

// ============ K_FRONT: mean + slr GEMM + out-bias + x-transpose ==============
// 2 blocks per batch: both stage full x (for mean), each does 128 GEMM rows.
#define XSP 65
#define KF_SMEM ((VV * XSP + 128 * NSLR + 64 + 256 + NSLR) * 4)
__global__ void k_front(const float* __restrict__ x,
                        const float* __restrict__ W,
                        const float* __restrict__ bias,
                        const float* __restrict__ W_out,
                        const float* __restrict__ b_out) {
    extern __shared__ float sh[];
    float* xs   = sh;                       // [256][65]
    float* Wsh  = xs + VV * XSP;            // [128][68]
    float* mean = Wsh + 128 * NSLR;         // [64]
    float* red  = mean + 64;                // [256]
    float* cc   = red + 256;                // [68]
    int b = blockIdx.x >> 1;
    int h = blockIdx.x & 1;                 // row half
    int t = threadIdx.x;

    const float* xb = x + (size_t)b * VV * FF;
    for (int e = t; e < VV * FF; e += 256) {
        int row = e >> 6, c = e & 63;
        xs[row * XSP + c] = xb[e];
    }
    for (int e = t; e < 128 * NSLR; e += 256) Wsh[e] = W[e];
    __syncthreads();

    // x-part of transposed fp: this block writes its half of v range
    {
        float* dst = g_fpT + (size_t)b * KOUT * VV + h * 128;
        for (int e = t; e < FF * 128; e += 256) {
            int k = e >> 7, r = e & 127;
            dst[k * VV + r] = xs[(h * 128 + r) * XSP + k];
        }
    }

    {
        int f = t & 63, vg = t >> 6;
        float acc = 0.f;
        #pragma unroll 8
        for (int v = vg * 64; v < vg * 64 + 64; v++) acc += xs[v * XSP + f];
        red[vg * 64 + f] = acc;
    }
    __syncthreads();
    if (t < 64) {
        float m = (red[t] + red[64 + t] + red[128 + t] + red[192 + t]) * (1.0f / VV);
        mean[t] = m;
        if (h == 0) g_mx[b * FF + t] = m;
    }
    __syncthreads();

    if (t < NSLR) {
        float acc = bias[t];
        #pragma unroll 8
        for (int k = 0; k < 64; k++) acc += mean[k] * Wsh[(64 + k) * NSLR + t];
        cc[t] = acc;
    }
    if (h == 0 && t < NOUT) {
        float acc = b_out[t];
        const float* wr = W_out + 64 * NOUT + t;
        #pragma unroll 16
        for (int k = 0; k < 64; k++) acc += mean[k] * wr[k * NOUT];
        g_bb[b * NOUT + t] = acc;
    }
    __syncthreads();

    // GEMM for 128 rows: thread = 2 rows x 17 cols
    int rg = t >> 2;                 // 0..63 -> rows h*128 + rg*2, +1
    int cg = t & 3;                  // cols cg*17..cg*17+16
    int r0 = h * 128 + rg * 2;
    float acc[2][17];
    #pragma unroll
    for (int u = 0; u < 17; u++) {
        float c0 = cc[cg * 17 + u];
        acc[0][u] = c0; acc[1][u] = c0;
    }
    const float* xr = xs + r0 * XSP;
    #pragma unroll 4
    for (int k = 0; k < 64; k++) {
        float a0 = xr[k], a1 = xr[XSP + k];
        const float* wrow = Wsh + k * NSLR + cg * 17;
        #pragma unroll
        for (int u = 0; u < 17; u++) {
            float w = wrow[u];
            acc[0][u] += a0 * w; acc[1][u] += a1 * w;
        }
    }
    #pragma unroll
    for (int q = 0; q < 2; q++) {
        int bv = b * VV + r0 + q;
        #pragma unroll
        for (int u = 0; u < 17; u++) {
            int col = cg * 17 + u;
            float v = fmaxf(acc[q][u], 0.f);
            if (col < NS) g_s [bv * NS  + col]       = v;
            else          g_lr[bv * NLR + col - NS]  = v;
        }
    }
}

// ============ K_SEL: warp-per-row top-40 by (d2, idx) ========================
__global__ void k_sel() {
    __shared__ float4 s_sh[VV];
    int b = blockIdx.x >> 5;
    int i = ((blockIdx.x & 31) << 3) + (threadIdx.x >> 5);
    int l = threadIdx.x & 31;
    if (threadIdx.x < VV)
        s_sh[threadIdx.x] = ((const float4*)g_s)[b * VV + threadIdx.x];
    __syncthreads();

    float4 sv = s_sh[i];
    float d2[8]; unsigned bits[8];
    #pragma unroll
    for (int q = 0; q < 8; q++) {
        float4 sj = s_sh[q * 32 + l];
        float dx = sv.x - sj.x, dy = sv.y - sj.y, dz = sv.z - sj.z, dw = sv.w - sj.w;
        d2[q] = dx * dx + dy * dy + dz * dz + dw * dw;
        bits[q] = __float_as_uint(d2[q]);
    }
    // binary search: smallest thr with count(bits <= thr) >= 40
    unsigned lo = 0u, hi = 0xFFFFFFFFu;
    #pragma unroll 1
    for (int it = 0; it < 32; it++) {
        unsigned mid = lo + ((hi - lo) >> 1);
        int c = 0;
        #pragma unroll
        for (int q = 0; q < 8; q++) c += (bits[q] <= mid);
        c = __reduce_add_sync(0xFFFFFFFFu, c);
        if (c >= KNB) hi = mid; else lo = mid + 1u;
    }
    unsigned thr = lo;
    int cl = 0;
    #pragma unroll
    for (int q = 0; q < 8; q++) cl += (bits[q] < thr);
    cl = __reduce_add_sync(0xFFFFFFFFu, cl);
    int need = KNB - cl;

    // tie-break index via ballot scan: need-th smallest index with bits==thr
    int jthr = VV - 1;
    {
        int cum = 0;
        bool done = false;
        #pragma unroll
        for (int q = 0; q < 8; q++) {
            unsigned mq = __ballot_sync(0xFFFFFFFFu, bits[q] == thr);
            int c = __popc(mq);
            if (!done && cum + c >= need) {
                int pos = __fns(mq, 0, need - cum);
                jthr = q * 32 + pos;
                done = true;
            }
            cum += c;
        }
    }

    int row = b * VV + i;
    int base = 0;
    #pragma unroll
    for (int q = 0; q < 8; q++) {
        int j = q * 32 + l;
        bool sel = (bits[q] < thr) || (bits[q] == thr && j <= jthr);
        unsigned bal = __ballot_sync(0xFFFFFFFFu, sel);
        if (sel) {
            int pos = base + __popc(bal & ((1u << l) - 1u));
            g_nidx[row * KNB + pos] = j;
            g_nw  [row * KNB + pos] = __expf(-10.0f * d2[q]);
        }
        base += __popc(bal);
    }
}

// ============ K_AGG: thread-per-row weighted mean/max, 2 blocks/batch ========
#define LRP 68
#define SIP 129
#define HR  128
#define KA_SMEM ((VV * LRP + 2 * KNB * SIP) * 4)
__global__ void k_agg() {
    extern __shared__ float sh[];
    float* lr_sh = sh;                       // [256][68]
    float* sw    = sh + VV * LRP;            // [40][129]
    int*   sidx  = (int*)(sw + KNB * SIP);   // [40][129]
    int b = blockIdx.x >> 1;
    int q = blockIdx.x & 1;
    int t = threadIdx.x;

    const float* lrg = g_lr + (size_t)b * VV * NLR;
    for (int e = t; e < VV * NLR; e += 256) {
        int r = e >> 6, c = e & 63;
        lr_sh[r * LRP + c] = lrg[e];
    }
    const int*   gi = g_nidx + ((size_t)b * VV + q * HR) * KNB;
    const float* gw = g_nw   + ((size_t)b * VV + q * HR) * KNB;
    for (int e = t; e < HR * KNB; e += 256) {
        int r = e / KNB, k = e - r * KNB;
        sidx[k * SIP + r] = gi[e];
        sw  [k * SIP + r] = gw[e];
    }
    __syncthreads();

    int il = t & 127;                        // local row
    int i  = q * HR + il;                    // global row in batch
    int ch = (t >> 7) * 32;                  // feature chunk base (0 or 32)

    float* dm = g_fpT + (size_t)b * KOUT * VV + (size_t)64  * VV + i;
    float* dx = g_fpT + (size_t)b * KOUT * VV + (size_t)128 * VV + i;
    #pragma unroll
    for (int cc = 0; cc < 32; cc += 16) {
        int c0 = ch + cc;
        float m[16], mx[16];
        #pragma unroll
        for (int f = 0; f < 16; f++) { m[f] = 0.f; mx[f] = 0.f; }
        for (int k = 0; k < KNB; k++) {
            int   j = sidx[k * SIP + il];
            float w = sw  [k * SIP + il];
            const float4* rowp = (const float4*)&lr_sh[j * LRP + c0];
            #pragma unroll
            for (int qq = 0; qq < 4; qq++) {
                float4 lv = rowp[qq];
                float v0 = lv.x * w, v1 = lv.y * w, v2 = lv.z * w, v3 = lv.w * w;
                m [qq*4+0] += v0; m [qq*4+1] += v1; m [qq*4+2] += v2; m [qq*4+3] += v3;
                mx[qq*4+0] = fmaxf(mx[qq*4+0], v0);
                mx[qq*4+1] = fmaxf(mx[qq*4+1], v1);
                mx[qq*4+2] = fmaxf(mx[qq*4+2], v2);
                mx[qq*4+3] = fmaxf(mx[qq*4+3], v3);
            }
        }
        #pragma unroll
        for (int f = 0; f < 16; f++) {
            dm[(c0 + f) * VV] = m[f] * (1.0f / KNB);
            dx[(c0 + f) * VV] = mx[f];
        }
    }
}

// ============ K_OUT: out = relu(fpT^T @ W + bb), prefetched W ================
#define ROWS_O 32
#define KO_SMEM ((KOUT * ROWS_O + NOUT) * 4)

#define KOUT_BODY(KIDX, W4)                                                     \
    {                                                                           \
        const float* base_ = fb + (KIDX) * ROWS_O;                              \
        ull a0 = *(const ull*)(base_);                                          \
        ull a1 = *(const ull*)(base_ + 2);                                      \
        ull a2 = *(const ull*)(base_ + 4);                                      \
        ull a3 = *(const ull*)(base_ + 6);                                      \
        ull w0 = pack2((W4).x, (W4).x), w1 = pack2((W4).y, (W4).y);             \
        ull w2 = pack2((W4).z, (W4).z), w3 = pack2((W4).w, (W4).w);             \
        fma2(acc[0][0], a0, w0); fma2(acc[1][0], a1, w0);                       \
        fma2(acc[2][0], a2, w0); fma2(acc[3][0], a3, w0);                       \
        fma2(acc[0][1], a0, w1); fma2(acc[1][1], a1, w1);                       \
        fma2(acc[2][1], a2, w1); fma2(acc[3][1], a3, w1);                       \
        fma2(acc[0][2], a0, w2); fma2(acc[1][2], a1, w2);                       \
        fma2(acc[2][2], a2, w2); fma2(acc[3][2], a3, w2);                       \
        fma2(acc[0][3], a0, w3); fma2(acc[1][3], a1, w3);                       \
        fma2(acc[2][3], a2, w3); fma2(acc[3][3], a3, w3);                       \
    }

__global__ __launch_bounds__(128, 7)
void k_out(const float* __restrict__ W,
           float* __restrict__ out) {
    extern __shared__ float sh[];
    float* fs  = sh;                     // [192][32]
    float* bbs = fs + KOUT * ROWS_O;     // [128]
    int t   = threadIdx.x;
    int bv0 = blockIdx.x * ROWS_O;
    int b   = bv0 >> 8;

    const float* src = g_fpT + (size_t)b * KOUT * VV + (bv0 & 255);
    #pragma unroll 12
    for (int e = t; e < KOUT * ROWS_O; e += 128) {
        int k = e >> 5, r = e & 31;
        fs[e] = src[k * VV + r];
    }
    bbs[t] = g_bb[b * NOUT + t];
    __syncthreads();

    int rg = t >> 5;     // 4 rowgroups x 8 rows
    int cg = t & 31;     // 32 colgroups x 4 cols

    ull acc[4][4];       // [rowpair][col]
    #pragma unroll
    for (int c = 0; c < 4; c++) {
        float bv = bbs[cg * 4 + c];
        ull bp = pack2(bv, bv);
        #pragma unroll
        for (int rp = 0; rp < 4; rp++) acc[rp][c] = bp;
    }

    const float*  fb = fs + rg * 8;
    const float4* wp = (const float4*)(W) + cg;

    float4 w4 = __ldg(wp);                            // row 0
    #pragma unroll 8
    for (int k = 0; k < 63; k++) {
        float4 wn = __ldg(wp + (size_t)(k + 1) * 32);
        KOUT_BODY(k, w4);
        w4 = wn;
    }
    {
        float4 wn = __ldg(wp + (size_t)128 * 32);
        KOUT_BODY(63, w4);
        w4 = wn;
    }
    #pragma unroll 8
    for (int k = 64; k < 191; k++) {
        float4 wn = __ldg(wp + (size_t)(k + 65) * 32);
        KOUT_BODY(k, w4);
        w4 = wn;
    }
    KOUT_BODY(191, w4);

    #pragma unroll
    for (int rp = 0; rp < 4; rp++) {
        float lo0, hi0, lo1, hi1, lo2, hi2, lo3, hi3;
        unpack2(acc[rp][0], lo0, hi0);
        unpack2(acc[rp][1], lo1, hi1);
        unpack2(acc[rp][2], lo2, hi2);
        unpack2(acc[rp][3], lo3, hi3);
        float4 o0, o1;
        o0.x = fmaxf(lo0, 0.f); o0.y = fmaxf(lo1, 0.f);
        o0.z = fmaxf(lo2, 0.f); o0.w = fmaxf(lo3, 0.f);
        o1.x = fmaxf(hi0, 0.f); o1.y = fmaxf(hi1, 0.f);
        o1.z = fmaxf(hi2, 0.f); o1.w = fmaxf(hi3, 0.f);
        int r0 = bv0 + rg * 8 + rp * 2;
        *(float4*)(out + (size_t)r0 * NOUT + cg * 4)       = o0;
        *(float4*)(out + (size_t)(r0 + 1) * NOUT + cg * 4) = o1;
    }
}

// ---------------- launch ------------------------------------------------------
extern "C" void kernel_launch(void* const* d_in, const int* in_sizes, int n_in,
                              void* d_out, int out_size) {
    const float* x     = (const float*)d_in[0];
    const float* W_slr = (const float*)d_in[1];
    const float* b_slr = (const float*)d_in[2];
    const float* W_out = (const float*)d_in[3];
    const float* b_out = (const float*)d_in[4];
    float* out = (float*)d_out;

    static bool attr_done = false;
    if (!attr_done) {
        cudaFuncSetAttribute(k_front, cudaFuncAttributeMaxDynamicSharedMemorySize, KF_SMEM);
        cudaFuncSetAttribute(k_agg,   cudaFuncAttributeMaxDynamicSharedMemorySize, KA_SMEM);
        cudaFuncSetAttribute(k_out,   cudaFuncAttributeMaxDynamicSharedMemorySize, KO_SMEM);
        attr_done = true;
    }

    k_front<<<BB * 2, 256, KF_SMEM>>>(x, W_slr, b_slr, W_out, b_out);
    k_sel  <<<BB * VV / 8, 256>>>();
    k_agg  <<<BB * 2, 256, KA_SMEM>>>();
    k_out  <<<BB * VV / ROWS_O, 128, KO_SMEM>>>(W_out, out);
}